// round 8
// baseline (speedup 1.0000x reference)
#include <cuda_runtime.h>
#include <cuda_bf16.h>
#include <cstdint>

// Problem constants
#define Bv   32
#define Nv   128
#define Fv   78
#define Hv   256
#define Sv   20
#define Tv   13
#define Lv   3
#define ALPHA 0.2f
#define NEG_INF -9000000000000000.0f

#define BN (Bv*Nv)          // 4096 rows

// Scratch (device globals; no allocation allowed)
// Activations transposed AND duplicated: g_x2[c][2*row] = {v, v}
__device__ float g_x2[(size_t)Hv*2*BN];
// Projected h duplicated along columns: g_h2[row][2*c] = {v, v}
__device__ float g_h2[(size_t)BN*2*Hv];
__device__ float g_zbuf[Lv*2*BN + Bv*Hv];     // s1/s2 per layer + graph accum

#define GRAPH_OFF (Lv*2*BN)

// ---------------------------------------------------------------------------
// packed fp32x2 helpers
// ---------------------------------------------------------------------------
typedef unsigned long long u64;

__device__ __forceinline__ void fma2(u64& d, u64 a, u64 b) {
    asm("fma.rn.f32x2 %0, %1, %2, %0;" : "+l"(d) : "l"(a), "l"(b));
}
__device__ __forceinline__ u64 pack2(float lo, float hi) {
    u64 r;
    asm("mov.b64 %0, {%1, %2};" : "=l"(r) : "f"(lo), "f"(hi));
    return r;
}
__device__ __forceinline__ float2 unpack2(u64 p) {
    float lo, hi;
    asm("mov.b64 {%0, %1}, %2;" : "=f"(lo), "=f"(hi) : "l"(p));
    return make_float2(lo, hi);
}

// cp.async helpers
__device__ __forceinline__ void cp16(uint32_t s, const void* g) {
    asm volatile("cp.async.ca.shared.global [%0], [%1], 16;" :: "r"(s), "l"(g));
}
#define CP_COMMIT() asm volatile("cp.async.commit_group;")
#define CP_WAIT1()  asm volatile("cp.async.wait_group 1;")
#define CP_WAIT0()  asm volatile("cp.async.wait_group 0;")

// ---------------------------------------------------------------------------
// K1: x = node_features @ W_node + b_node -> g_x2 (transposed, duplicated)
// ---------------------------------------------------------------------------
#define NP_ROWS 8
__global__ void k_node_proj(const float* __restrict__ nf,
                            const float* __restrict__ W,
                            const float* __restrict__ bias)
{
    int row0 = blockIdx.x * NP_ROWS;
    int j    = threadIdx.x;

    __shared__ __align__(16) float sf[Fv * NP_ROWS];   // [f][r]
    __shared__ float st[NP_ROWS * 257];                // transpose tile

    for (int idx = j; idx < Fv*NP_ROWS; idx += 256) {
        int f = idx >> 3, r = idx & 7;
        sf[idx] = nf[(row0 + r)*Fv + f];
    }
    __syncthreads();

    float bj = bias[j];
    float acc[NP_ROWS];
#pragma unroll
    for (int r = 0; r < NP_ROWS; ++r) acc[r] = bj;

#pragma unroll 6
    for (int f = 0; f < Fv; ++f) {
        float w = W[f*Hv + j];
        const float4* xp = reinterpret_cast<const float4*>(&sf[f*NP_ROWS]);
        float4 xa = xp[0], xb = xp[1];
        acc[0] += xa.x * w;  acc[1] += xa.y * w;
        acc[2] += xa.z * w;  acc[3] += xa.w * w;
        acc[4] += xb.x * w;  acc[5] += xb.y * w;
        acc[6] += xb.z * w;  acc[7] += xb.w * w;
    }

#pragma unroll
    for (int r = 0; r < NP_ROWS; ++r)
        st[r*257 + j] = acc[r];
    __syncthreads();
    int r  = j & 7;
    int cb = j >> 3;          // 0..31
#pragma unroll
    for (int p = 0; p < 8; ++p) {
        int c = cb + 32*p;
        float v = st[r*257 + c];
        *reinterpret_cast<float2*>(
            &g_x2[(size_t)c*2*BN + 2*(row0 + r)]) = make_float2(v, v);
    }
}

// ---------------------------------------------------------------------------
// K2: h = x @ gat_W[l] + partial scores.
// 128 threads, tile 64 rows x 64 cols, thread = 4 rows x 8 cols, f32x2,
// x read PRE-DUPLICATED from g_x2 (no pack instrs in inner loop).
// ---------------------------------------------------------------------------
#define KCp 32
__global__ void __launch_bounds__(128)
k_gat_proj(const float* __restrict__ W,   // [256,256]
           const float* __restrict__ a,   // [512]
           int layer)
{
    const int row0 = blockIdx.x * 64;
    const int c0   = blockIdx.y * 64;
    const int t  = threadIdx.x;           // 0..127
    const int tx = t & 7, ty = t >> 3;    // tx 0..7 (cols), ty 0..15 (rows)

    float* s1 = g_zbuf + layer*2*BN;
    float* s2 = s1 + BN;

    __shared__ __align__(16) float sx[2][KCp*128];  // [k][2*row] duplicated
    __shared__ __align__(16) float sw[2][KCp*64];   // [k][col]

    const uint32_t sxa = (uint32_t)__cvta_generic_to_shared(sx);
    const uint32_t swa = (uint32_t)__cvta_generic_to_shared(sw);
    const float* x2 = g_x2;

#define ISSUE_CHUNK(kc, buf)                                                   \
    {                                                                          \
        _Pragma("unroll")                                                      \
        for (int m = 0; m < 8; ++m) {   /* x: 32k x 32 pieces */               \
            int idx = t + 128*m;                                               \
            int k = idx >> 5, f = idx & 31;                                    \
            uint32_t off = ((buf)*KCp*128 + k*128 + f*4)*4;                    \
            cp16(sxa + off, &x2[(size_t)((kc)+k)*2*BN + 2*row0 + f*4]);        \
        }                                                                      \
        _Pragma("unroll")                                                      \
        for (int m = 0; m < 4; ++m) {   /* w: 32k x 16 pieces */               \
            int idx = t + 128*m;                                               \
            int k = idx >> 4, f = idx & 15;                                    \
            uint32_t off = ((buf)*KCp*64 + k*64 + f*4)*4;                      \
            cp16(swa + off, &W[((kc)+k)*Hv + c0 + f*4]);                       \
        }                                                                      \
        CP_COMMIT();                                                           \
    }

    u64 acc[4][4];
#pragma unroll
    for (int r = 0; r < 4; ++r)
#pragma unroll
        for (int p = 0; p < 4; ++p) acc[r][p] = pack2(0.f, 0.f);

    ISSUE_CHUNK(0, 0);

    const int NCH = Hv / KCp;      // 8
#pragma unroll
    for (int c = 0; c < NCH; ++c) {
        const int cur = c & 1;
        if (c + 1 < NCH) {
            ISSUE_CHUNK((c+1)*KCp, (c+1)&1);
            CP_WAIT1();
        } else {
            CP_WAIT0();
        }
        __syncthreads();

#pragma unroll 8
        for (int k = 0; k < KCp; ++k) {
            // x duplicated: rows ty*4..ty*4+3 as 4 packed (v,v) u64s
            const u64* xp = reinterpret_cast<const u64*>(&sx[cur][k*128 + ty*8]);
            u64 x0 = xp[0], x1 = xp[1], x2r = xp[2], x3 = xp[3];
            const u64* wp = reinterpret_cast<const u64*>(&sw[cur][k*64 + tx*4]);
            const u64* wq = reinterpret_cast<const u64*>(&sw[cur][k*64 + 32 + tx*4]);
            u64 w0 = wp[0], w1 = wp[1], w2 = wq[0], w3 = wq[1];
            fma2(acc[0][0], x0, w0); fma2(acc[0][1], x0, w1);
            fma2(acc[0][2], x0, w2); fma2(acc[0][3], x0, w3);
            fma2(acc[1][0], x1, w0); fma2(acc[1][1], x1, w1);
            fma2(acc[1][2], x1, w2); fma2(acc[1][3], x1, w3);
            fma2(acc[2][0], x2r, w0); fma2(acc[2][1], x2r, w1);
            fma2(acc[2][2], x2r, w2); fma2(acc[2][3], x2r, w3);
            fma2(acc[3][0], x3, w0); fma2(acc[3][1], x3, w1);
            fma2(acc[3][2], x3, w2); fma2(acc[3][3], x3, w3);
        }
        __syncthreads();
    }
#undef ISSUE_CHUNK

    // epilogue: store h duplicated, atomic partial scores
    float4 a1a = *reinterpret_cast<const float4*>(&a[c0 + tx*4]);
    float4 a1b = *reinterpret_cast<const float4*>(&a[c0 + 32 + tx*4]);
    float4 a2a = *reinterpret_cast<const float4*>(&a[Hv + c0 + tx*4]);
    float4 a2b = *reinterpret_cast<const float4*>(&a[Hv + c0 + 32 + tx*4]);

#pragma unroll
    for (int r = 0; r < 4; ++r) {
        int row = row0 + ty*4 + r;
        float2 v0 = unpack2(acc[r][0]);
        float2 v1 = unpack2(acc[r][1]);
        float2 v2 = unpack2(acc[r][2]);
        float2 v3 = unpack2(acc[r][3]);
        float* hp = &g_h2[(size_t)row*2*Hv + 2*c0];
        *reinterpret_cast<float4*>(hp + 8*tx)     = make_float4(v0.x, v0.x, v0.y, v0.y);
        *reinterpret_cast<float4*>(hp + 8*tx + 4) = make_float4(v1.x, v1.x, v1.y, v1.y);
        *reinterpret_cast<float4*>(hp + 64 + 8*tx)     = make_float4(v2.x, v2.x, v2.y, v2.y);
        *reinterpret_cast<float4*>(hp + 64 + 8*tx + 4) = make_float4(v3.x, v3.x, v3.y, v3.y);

        float p1 = v0.x*a1a.x + v0.y*a1a.y + v1.x*a1a.z + v1.y*a1a.w
                 + v2.x*a1b.x + v2.y*a1b.y + v3.x*a1b.z + v3.y*a1b.w;
        float p2 = v0.x*a2a.x + v0.y*a2a.y + v1.x*a2a.z + v1.y*a2a.w
                 + v2.x*a2b.x + v2.y*a2b.y + v3.x*a2b.z + v3.y*a2b.w;
#pragma unroll
        for (int off = 4; off > 0; off >>= 1) {
            p1 += __shfl_xor_sync(0xffffffffu, p1, off);
            p2 += __shfl_xor_sync(0xffffffffu, p2, off);
        }
        if (tx == 0) {
            atomicAdd(&s1[row], p1);
            atomicAdd(&s2[row], p2);
        }
    }
}

// ---------------------------------------------------------------------------
// K3: softmax attention + aggregation (+ fused mean on last layer)
// 128 threads, tile 64 att-rows x 64 channels, thread = 8 rows x 4 cols.
// att read as contiguous row-pairs; h read PRE-DUPLICATED from g_h2.
// ---------------------------------------------------------------------------
#define JCc 16
#define ATS 68
__global__ void __launch_bounds__(128)
k_gat_agg(const int* __restrict__ adj, int layer, int last)
{
    const int b  = blockIdx.z;
    const int i0 = blockIdx.x * 64;
    const int c0 = blockIdx.y * 64;
    const int t  = threadIdx.x;            // 0..127
    const int tx = t & 15, ty = t >> 4;    // tx 0..15 (col grp), ty 0..7 (row grp)
    const int lane = t & 31, warp = t >> 5;

    const float* s1 = g_zbuf + layer*2*BN;
    const float* s2 = s1 + BN;

    __shared__ __align__(16) float s2_sh[Nv];
    __shared__ __align__(16) float att[Nv * ATS];     // [j][i_local]
    __shared__ __align__(16) float sh[2][JCc * 128];  // h chunks [j][2*c] dup

    const uint32_t sha = (uint32_t)__cvta_generic_to_shared(sh);
    const float* h2 = g_h2 + (size_t)b*Nv*2*Hv;

#define ISSUE_H(jc, buf)                                                       \
    {                                                                          \
        _Pragma("unroll")                                                      \
        for (int m = 0; m < 4; ++m) {   /* 16j x 32 pieces */                  \
            int idx = t + 128*m;                                               \
            int k = idx >> 5, f = idx & 31;                                    \
            uint32_t off = ((buf)*JCc*128 + k*128 + f*4)*4;                    \
            cp16(sha + off, &h2[(size_t)((jc)+k)*2*Hv + 2*c0 + f*4]);          \
        }                                                                      \
        CP_COMMIT();                                                           \
    }

    ISSUE_H(0, 0);       // overlap with softmax

    s2_sh[t] = s2[b*Nv + t];
    __syncthreads();

    // softmax: 16 rows per warp (4 warps x 16 = 64 rows); int4 adj loads
#pragma unroll 4
    for (int rr = 0; rr < 16; ++rr) {
        int il = warp*16 + rr;
        int i  = i0 + il;
        float s1i = s1[b*Nv + i];
        const int* adj_row = adj + (size_t)(b*Nv + i)*Nv;
        int4   am  = *reinterpret_cast<const int4*>(&adj_row[lane*4]);
        float4 s2v = *reinterpret_cast<const float4*>(&s2_sh[lane*4]);
        float e[4];
        {
            float v0 = s1i + s2v.x, v1 = s1i + s2v.y;
            float v2 = s1i + s2v.z, v3 = s1i + s2v.w;
            v0 = (v0 > 0.f) ? v0 : ALPHA*v0;  v1 = (v1 > 0.f) ? v1 : ALPHA*v1;
            v2 = (v2 > 0.f) ? v2 : ALPHA*v2;  v3 = (v3 > 0.f) ? v3 : ALPHA*v3;
            e[0] = (am.x > 0) ? v0 : NEG_INF;
            e[1] = (am.y > 0) ? v1 : NEG_INF;
            e[2] = (am.z > 0) ? v2 : NEG_INF;
            e[3] = (am.w > 0) ? v3 : NEG_INF;
        }
        float mx = fmaxf(fmaxf(e[0], e[1]), fmaxf(e[2], e[3]));
#pragma unroll
        for (int off = 16; off > 0; off >>= 1)
            mx = fmaxf(mx, __shfl_xor_sync(0xffffffffu, mx, off));
        float sum = 0.f;
#pragma unroll
        for (int q = 0; q < 4; ++q) { e[q] = __expf(e[q] - mx); sum += e[q]; }
#pragma unroll
        for (int off = 16; off > 0; off >>= 1)
            sum += __shfl_xor_sync(0xffffffffu, sum, off);
        float inv = 1.f / sum;
#pragma unroll
        for (int q = 0; q < 4; ++q)
            att[(lane*4 + q)*ATS + il] = e[q] * inv;
    }

    // acc[rp][cq]: rp = row-pair (rows ty*8+2rp, +1), cq = col (c0+tx*4+cq)
    u64 acc[4][4];
#pragma unroll
    for (int r = 0; r < 4; ++r)
#pragma unroll
        for (int p = 0; p < 4; ++p) acc[r][p] = pack2(0.f, 0.f);

    const int NJC = Nv / JCc;      // 8
#pragma unroll
    for (int c = 0; c < NJC; ++c) {
        const int cur = c & 1;
        if (c + 1 < NJC) {
            ISSUE_H((c+1)*JCc, (c+1)&1);
            CP_WAIT1();
        } else {
            CP_WAIT0();
        }
        __syncthreads();

#pragma unroll 8
        for (int k = 0; k < JCc; ++k) {
            int j = c*JCc + k;
            // att row-pairs (contiguous): rows ty*8 .. ty*8+7 as 4 u64 pairs
            const u64* ap = reinterpret_cast<const u64*>(&att[j*ATS + ty*8]);
            u64 a0 = ap[0], a1 = ap[1], a2 = ap[2], a3 = ap[3];
            // h duplicated: cols tx*4..tx*4+3 as 4 (v,v) u64s
            const u64* hp = reinterpret_cast<const u64*>(&sh[cur][k*128 + tx*8]);
            u64 h0 = hp[0], h1 = hp[1], h2r = hp[2], h3 = hp[3];
            fma2(acc[0][0], a0, h0); fma2(acc[0][1], a0, h1);
            fma2(acc[0][2], a0, h2r); fma2(acc[0][3], a0, h3);
            fma2(acc[1][0], a1, h0); fma2(acc[1][1], a1, h1);
            fma2(acc[1][2], a1, h2r); fma2(acc[1][3], a1, h3);
            fma2(acc[2][0], a2, h0); fma2(acc[2][1], a2, h1);
            fma2(acc[2][2], a2, h2r); fma2(acc[2][3], a2, h3);
            fma2(acc[3][0], a3, h0); fma2(acc[3][1], a3, h1);
            fma2(acc[3][2], a3, h2r); fma2(acc[3][3], a3, h3);
        }
        __syncthreads();
    }
#undef ISSUE_H

    // acc[rp][cq] = (out[row=ty*8+2rp][col], out[row+1][col])
    if (last) {
        float* graph = g_zbuf + GRAPH_OFF;
#pragma unroll
        for (int cq = 0; cq < 4; ++cq) {
            float p = 0.f;
#pragma unroll
            for (int rp = 0; rp < 4; ++rp) {
                float2 v = unpack2(acc[rp][cq]);
                p += fmaxf(v.x, 0.f) + fmaxf(v.y, 0.f);
            }
            atomicAdd(&graph[b*Hv + c0 + tx*4 + cq], p);
        }
    } else {
        // transpose relu through smem (reuse att as st[i][c], stride 68)
        __syncthreads();
        float* st = att;
#pragma unroll
        for (int rp = 0; rp < 4; ++rp) {
            int i = ty*8 + 2*rp;
#pragma unroll
            for (int cq = 0; cq < 4; ++cq) {
                float2 v = unpack2(acc[rp][cq]);
                st[i*ATS + tx*4 + cq]     = fmaxf(v.x, 0.f);
                st[(i+1)*ATS + tx*4 + cq] = fmaxf(v.y, 0.f);
            }
        }
        __syncthreads();
        // thread t: channel ch = t&63, half = t>>6 -> 32 rows each, duplicated
        int ch   = t & 63;
        int half = t >> 6;
        float* dst = &g_x2[(size_t)(c0 + ch)*2*BN + 2*(b*Nv + i0) + half*64];
#pragma unroll
        for (int q = 0; q < 16; ++q) {
            int i = half*32 + 2*q;
            float v0 = st[i*ATS + ch], v1 = st[(i+1)*ATS + ch];
            *reinterpret_cast<float4*>(dst + 4*q) = make_float4(v0, v0, v1, v1);
        }
    }
}

// ---------------------------------------------------------------------------
// K5: fused head. One block per batch element.
// ---------------------------------------------------------------------------
__global__ void k_head(const float* __restrict__ scaffold,
                       const float* __restrict__ W_sc,
                       const float* __restrict__ b_sc,
                       const float* __restrict__ gp_w1,
                       const float* __restrict__ gp_b1,
                       const float* __restrict__ gp_w2,
                       const float* __restrict__ gp_b2,
                       const float* __restrict__ out_w1,
                       const float* __restrict__ out_b1,
                       const float* __restrict__ out_w2,
                       const float* __restrict__ out_b2,
                       float* __restrict__ out)
{
    int b = blockIdx.x, t = threadIdx.x;
    const float* graph = g_zbuf + GRAPH_OFF;
    __shared__ float scaf[Sv];
    __shared__ float grow[Hv];
    __shared__ float sc[Hv];
    __shared__ float g1[128], sp1[128];
    __shared__ float c[128];
    __shared__ float hdn[128];

    if (t < Sv) scaf[t] = scaffold[b*Sv + t];
    grow[t] = graph[b*Hv + t] * (1.0f/Nv);
    __syncthreads();

    {
        float acc = b_sc[t];
#pragma unroll
        for (int k = 0; k < Sv; ++k)
            acc += scaf[k] * W_sc[k*Hv + t];
        sc[t] = acc;
    }
    __syncthreads();

    {
        int col = t & 127;
        const float* src = (t < 128) ? grow : sc;
        float acc = gp_b1[col];
#pragma unroll 4
        for (int k = 0; k < Hv; ++k)
            acc += src[k] * gp_w1[k*128 + col];
        acc = fmaxf(acc, 0.f);
        if (t < 128) g1[col] = acc; else sp1[col] = acc;
    }
    __syncthreads();

    if (t < 128) {
        int col = t & 63;
        const float* src = (t < 64) ? g1 : sp1;
        float acc = gp_b2[col];
#pragma unroll 4
        for (int k = 0; k < 128; ++k)
            acc += src[k] * gp_w2[k*64 + col];
        c[t] = fmaxf(acc, 0.f);
    }
    __syncthreads();

    if (t < 128) {
        float acc = out_b1[t];
#pragma unroll 4
        for (int k = 0; k < 128; ++k)
            acc += c[k] * out_w1[k*128 + t];
        hdn[t] = fmaxf(acc, 0.f);
    }
    __syncthreads();

    if (t < Tv) {
        float acc = out_b2[t];
#pragma unroll 4
        for (int k = 0; k < 128; ++k)
            acc += hdn[k] * out_w2[k*Tv + t];
        out[b*Tv + t] = acc;
    }
}

// ---------------------------------------------------------------------------
extern "C" void kernel_launch(void* const* d_in, const int* in_sizes, int n_in,
                              void* d_out, int out_size)
{
    const float* node_features     = (const float*)d_in[0];
    // d_in[1] = edge_features — unused by the reference
    const int*   adj_matrix        = (const int*)  d_in[2];
    const float* scaffold_features = (const float*)d_in[3];
    const float* W_node            = (const float*)d_in[4];
    const float* b_node            = (const float*)d_in[5];
    const float* gat_W             = (const float*)d_in[6];
    const float* gat_a             = (const float*)d_in[7];
    const float* W_sc              = (const float*)d_in[8];
    const float* b_sc              = (const float*)d_in[9];
    const float* gp_w1             = (const float*)d_in[10];
    const float* gp_b1             = (const float*)d_in[11];
    const float* gp_w2             = (const float*)d_in[12];
    const float* gp_b2             = (const float*)d_in[13];
    const float* out_w1            = (const float*)d_in[14];
    const float* out_b1            = (const float*)d_in[15];
    const float* out_w2            = (const float*)d_in[16];
    const float* out_b2            = (const float*)d_in[17];
    float* out = (float*)d_out;

    void* zp = nullptr;
    cudaGetSymbolAddress(&zp, g_zbuf);
    cudaMemsetAsync(zp, 0, (Lv*2*BN + Bv*Hv)*sizeof(float));

    k_node_proj<<<BN/NP_ROWS, 256>>>(node_features, W_node, b_node);

    for (int l = 0; l < Lv; ++l) {
        dim3 pg(BN/64, Hv/64);                 // 64 x 4 = 256 blocks, 128 thr
        k_gat_proj<<<pg, 128>>>(gat_W + (size_t)l*Hv*Hv,
                                gat_a + (size_t)l*2*Hv, l);
        dim3 ag(Nv/64, Hv/64, Bv);             // 2 x 4 x 32 = 256 blocks, 128 thr
        k_gat_agg<<<ag, 128>>>(adj_matrix, l, l == Lv-1);
    }

    k_head<<<Bv, 256>>>(scaffold_features, W_sc, b_sc,
                        gp_w1, gp_b1, gp_w2, gp_b2,
                        out_w1, out_b1, out_w2, out_b2, out);
}

// round 9
// speedup vs baseline: 1.0013x; 1.0013x over previous
#include <cuda_runtime.h>
#include <cuda_bf16.h>
#include <cstdint>

// Problem constants
#define Bv   32
#define Nv   128
#define Fv   78
#define Hv   256
#define Sv   20
#define Tv   13
#define Lv   3
#define ALPHA 0.2f
#define NEG_INF -9000000000000000.0f

#define BN (Bv*Nv)          // 4096 rows

// Scratch (device globals; no allocation allowed)
__device__ float g_xT[Hv*BN];                 // activations TRANSPOSED [c][row]
__device__ float g_h[BN*Hv];                  // projected h, normal [row][c]
__device__ float g_zbuf[Lv*2*BN + Bv*Hv];     // s1/s2 per layer + graph accum

#define GRAPH_OFF (Lv*2*BN)

// ---------------------------------------------------------------------------
// packed fp32x2 helpers
// ---------------------------------------------------------------------------
typedef unsigned long long u64;

__device__ __forceinline__ void fma2(u64& d, u64 a, u64 b) {
    asm("fma.rn.f32x2 %0, %1, %2, %0;" : "+l"(d) : "l"(a), "l"(b));
}
__device__ __forceinline__ u64 pack2(float lo, float hi) {
    u64 r;
    asm("mov.b64 %0, {%1, %2};" : "=l"(r) : "f"(lo), "f"(hi));
    return r;
}
__device__ __forceinline__ float2 unpack2(u64 p) {
    float lo, hi;
    asm("mov.b64 {%0, %1}, %2;" : "=f"(lo), "=f"(hi) : "l"(p));
    return make_float2(lo, hi);
}

// cp.async helpers
__device__ __forceinline__ void cp16(uint32_t s, const void* g) {
    asm volatile("cp.async.ca.shared.global [%0], [%1], 16;" :: "r"(s), "l"(g));
}
#define CP_COMMIT() asm volatile("cp.async.commit_group;")
#define CP_WAIT1()  asm volatile("cp.async.wait_group 1;")
#define CP_WAIT0()  asm volatile("cp.async.wait_group 0;")

// ---------------------------------------------------------------------------
// K1: x = node_features @ W_node + b_node -> g_xT (transposed)
// ---------------------------------------------------------------------------
#define NP_ROWS 8
__global__ void k_node_proj(const float* __restrict__ nf,
                            const float* __restrict__ W,
                            const float* __restrict__ bias)
{
    int row0 = blockIdx.x * NP_ROWS;
    int j    = threadIdx.x;

    __shared__ __align__(16) float sf[Fv * NP_ROWS];   // [f][r]
    __shared__ float st[NP_ROWS * 257];                // transpose tile

    for (int idx = j; idx < Fv*NP_ROWS; idx += 256) {
        int f = idx >> 3, r = idx & 7;
        sf[idx] = nf[(row0 + r)*Fv + f];
    }
    __syncthreads();

    float bj = bias[j];
    float acc[NP_ROWS];
#pragma unroll
    for (int r = 0; r < NP_ROWS; ++r) acc[r] = bj;

#pragma unroll 6
    for (int f = 0; f < Fv; ++f) {
        float w = W[f*Hv + j];
        const float4* xp = reinterpret_cast<const float4*>(&sf[f*NP_ROWS]);
        float4 xa = xp[0], xb = xp[1];
        acc[0] += xa.x * w;  acc[1] += xa.y * w;
        acc[2] += xa.z * w;  acc[3] += xa.w * w;
        acc[4] += xb.x * w;  acc[5] += xb.y * w;
        acc[6] += xb.z * w;  acc[7] += xb.w * w;
    }

#pragma unroll
    for (int r = 0; r < NP_ROWS; ++r)
        st[r*257 + j] = acc[r];
    __syncthreads();
    int r  = j & 7;
    int cb = j >> 3;          // 0..31
#pragma unroll
    for (int p = 0; p < 8; ++p) {
        int c = cb + 32*p;
        g_xT[(size_t)c*BN + row0 + r] = st[r*257 + c];
    }
}

// ---------------------------------------------------------------------------
// K2: h = x @ gat_W[l] + partial scores.
// 256 threads, tile 64 rows x 64 cols, thread = 2 rows x 8 cols, f32x2.
// ---------------------------------------------------------------------------
#define KCp 32
__global__ void __launch_bounds__(256)
k_gat_proj(const float* __restrict__ W,   // [256,256]
           const float* __restrict__ a,   // [512]
           int layer)
{
    const int row0 = blockIdx.x * 64;
    const int c0   = blockIdx.y * 64;
    const int t  = threadIdx.x;           // 0..255
    const int tx = t & 7, ty = t >> 3;    // tx 0..7 (col groups), ty 0..31 (row pairs)

    float* s1 = g_zbuf + layer*2*BN;
    float* s2 = s1 + BN;

    __shared__ __align__(16) float sx[2][KCp*64];   // [k][row]
    __shared__ __align__(16) float sw[2][KCp*64];   // [k][col]

    const uint32_t sxa = (uint32_t)__cvta_generic_to_shared(sx);
    const uint32_t swa = (uint32_t)__cvta_generic_to_shared(sw);
    const float* xT = g_xT;

    // staging: 512 x 16B per array per chunk, 256 threads -> 2 each
#define ISSUE_CHUNK(kc, buf)                                                   \
    {                                                                          \
        _Pragma("unroll")                                                      \
        for (int m = 0; m < 2; ++m) {                                          \
            int idx = t + 256*m;                                               \
            int k = idx >> 4, f = idx & 15;                                    \
            uint32_t off = ((buf)*KCp*64 + k*64 + f*4)*4;                      \
            cp16(sxa + off, &xT[(size_t)((kc)+k)*BN + row0 + f*4]);            \
            cp16(swa + off, &W[((kc)+k)*Hv + c0 + f*4]);                       \
        }                                                                      \
        CP_COMMIT();                                                           \
    }

    u64 acc[2][4];
#pragma unroll
    for (int r = 0; r < 2; ++r)
#pragma unroll
        for (int p = 0; p < 4; ++p) acc[r][p] = pack2(0.f, 0.f);

    ISSUE_CHUNK(0, 0);

    const int NCH = Hv / KCp;      // 8
#pragma unroll
    for (int c = 0; c < NCH; ++c) {
        const int cur = c & 1;
        if (c + 1 < NCH) {
            ISSUE_CHUNK((c+1)*KCp, (c+1)&1);
            CP_WAIT1();
        } else {
            CP_WAIT0();
        }
        __syncthreads();

#pragma unroll 8
        for (int k = 0; k < KCp; ++k) {
            float2 xa = *reinterpret_cast<const float2*>(&sx[cur][k*64 + ty*2]);
            const u64* wp = reinterpret_cast<const u64*>(&sw[cur][k*64 + tx*4]);
            const u64* wq = reinterpret_cast<const u64*>(&sw[cur][k*64 + 32 + tx*4]);
            u64 w0 = wp[0], w1 = wp[1], w2 = wq[0], w3 = wq[1];
            u64 x0 = pack2(xa.x, xa.x);
            u64 x1 = pack2(xa.y, xa.y);
            fma2(acc[0][0], x0, w0); fma2(acc[0][1], x0, w1);
            fma2(acc[0][2], x0, w2); fma2(acc[0][3], x0, w3);
            fma2(acc[1][0], x1, w0); fma2(acc[1][1], x1, w1);
            fma2(acc[1][2], x1, w2); fma2(acc[1][3], x1, w3);
        }
        __syncthreads();
    }
#undef ISSUE_CHUNK

    // epilogue: store h, reduce scores across the 8 tx lanes
    float4 a1a = *reinterpret_cast<const float4*>(&a[c0 + tx*4]);
    float4 a1b = *reinterpret_cast<const float4*>(&a[c0 + 32 + tx*4]);
    float4 a2a = *reinterpret_cast<const float4*>(&a[Hv + c0 + tx*4]);
    float4 a2b = *reinterpret_cast<const float4*>(&a[Hv + c0 + 32 + tx*4]);

#pragma unroll
    for (int r = 0; r < 2; ++r) {
        int row = row0 + ty*2 + r;
        float2 v0 = unpack2(acc[r][0]);
        float2 v1 = unpack2(acc[r][1]);
        float2 v2 = unpack2(acc[r][2]);
        float2 v3 = unpack2(acc[r][3]);
        *reinterpret_cast<float4*>(&g_h[(size_t)row*Hv + c0 + tx*4]) =
            make_float4(v0.x, v0.y, v1.x, v1.y);
        *reinterpret_cast<float4*>(&g_h[(size_t)row*Hv + c0 + 32 + tx*4]) =
            make_float4(v2.x, v2.y, v3.x, v3.y);

        float p1 = v0.x*a1a.x + v0.y*a1a.y + v1.x*a1a.z + v1.y*a1a.w
                 + v2.x*a1b.x + v2.y*a1b.y + v3.x*a1b.z + v3.y*a1b.w;
        float p2 = v0.x*a2a.x + v0.y*a2a.y + v1.x*a2a.z + v1.y*a2a.w
                 + v2.x*a2b.x + v2.y*a2b.y + v3.x*a2b.z + v3.y*a2b.w;
#pragma unroll
        for (int off = 4; off > 0; off >>= 1) {
            p1 += __shfl_xor_sync(0xffffffffu, p1, off);
            p2 += __shfl_xor_sync(0xffffffffu, p2, off);
        }
        if (tx == 0) {
            atomicAdd(&s1[row], p1);
            atomicAdd(&s2[row], p2);
        }
    }
}

// ---------------------------------------------------------------------------
// K3: softmax attention + aggregation (+ fused mean on last layer)
// 256 threads, tile 64 att-rows x 64 channels, thread = 2x8, f32x2.
// ---------------------------------------------------------------------------
#define JCc 32
#define ATS 68
__global__ void __launch_bounds__(256)
k_gat_agg(const int* __restrict__ adj, int layer, int last)
{
    const int b  = blockIdx.z;
    const int i0 = blockIdx.x * 64;
    const int c0 = blockIdx.y * 64;
    const int t  = threadIdx.x;            // 0..255
    const int tx = t & 7, ty = t >> 3;     // tx: col group, ty 0..31: row pairs
    const int lane = t & 31, warp = t >> 5;

    const float* s1 = g_zbuf + layer*2*BN;
    const float* s2 = s1 + BN;

    __shared__ __align__(16) float s2_sh[Nv];
    __shared__ __align__(16) float att[Nv * ATS];     // [j][i_local(64)]
    __shared__ __align__(16) float sh[2][JCc * 64];   // h chunks [j][c]

    const uint32_t sha = (uint32_t)__cvta_generic_to_shared(sh);
    const float* hb = g_h + (size_t)b*Nv*Hv;

#define ISSUE_H(jc, buf)                                                       \
    {                                                                          \
        _Pragma("unroll")                                                      \
        for (int m = 0; m < 2; ++m) {                                          \
            int idx = t + 256*m;                                               \
            int k = idx >> 4, f = idx & 15;                                    \
            uint32_t off = ((buf)*JCc*64 + k*64 + f*4)*4;                      \
            cp16(sha + off, &hb[(size_t)((jc)+k)*Hv + c0 + f*4]);              \
        }                                                                      \
        CP_COMMIT();                                                           \
    }

    ISSUE_H(0, 0);       // overlap with softmax

    if (t < Nv) s2_sh[t] = s2[b*Nv + t];
    __syncthreads();

    // softmax: 8 rows per warp (8 warps x 8 = 64 rows); int4 adj loads
#pragma unroll
    for (int rr = 0; rr < 8; ++rr) {
        int il = warp*8 + rr;
        int i  = i0 + il;
        float s1i = s1[b*Nv + i];
        const int* adj_row = adj + (size_t)(b*Nv + i)*Nv;
        int4   am  = *reinterpret_cast<const int4*>(&adj_row[lane*4]);
        float4 s2v = *reinterpret_cast<const float4*>(&s2_sh[lane*4]);
        float e[4];
        {
            float v0 = s1i + s2v.x, v1 = s1i + s2v.y;
            float v2 = s1i + s2v.z, v3 = s1i + s2v.w;
            v0 = (v0 > 0.f) ? v0 : ALPHA*v0;  v1 = (v1 > 0.f) ? v1 : ALPHA*v1;
            v2 = (v2 > 0.f) ? v2 : ALPHA*v2;  v3 = (v3 > 0.f) ? v3 : ALPHA*v3;
            e[0] = (am.x > 0) ? v0 : NEG_INF;
            e[1] = (am.y > 0) ? v1 : NEG_INF;
            e[2] = (am.z > 0) ? v2 : NEG_INF;
            e[3] = (am.w > 0) ? v3 : NEG_INF;
        }
        float mx = fmaxf(fmaxf(e[0], e[1]), fmaxf(e[2], e[3]));
#pragma unroll
        for (int off = 16; off > 0; off >>= 1)
            mx = fmaxf(mx, __shfl_xor_sync(0xffffffffu, mx, off));
        float sum = 0.f;
#pragma unroll
        for (int q = 0; q < 4; ++q) { e[q] = __expf(e[q] - mx); sum += e[q]; }
#pragma unroll
        for (int off = 16; off > 0; off >>= 1)
            sum += __shfl_xor_sync(0xffffffffu, sum, off);
        float inv = 1.f / sum;
#pragma unroll
        for (int q = 0; q < 4; ++q)
            att[(lane*4 + q)*ATS + il] = e[q] * inv;
    }

    u64 acc[2][4];
#pragma unroll
    for (int r = 0; r < 2; ++r)
#pragma unroll
        for (int p = 0; p < 4; ++p) acc[r][p] = pack2(0.f, 0.f);

    const int NJC = Nv / JCc;      // 4
#pragma unroll
    for (int c = 0; c < NJC; ++c) {
        const int cur = c & 1;
        if (c + 1 < NJC) {
            ISSUE_H((c+1)*JCc, (c+1)&1);
            CP_WAIT1();
        } else {
            CP_WAIT0();
        }
        __syncthreads();

#pragma unroll 8
        for (int k = 0; k < JCc; ++k) {
            int j = c*JCc + k;
            float2 ia = *reinterpret_cast<const float2*>(&att[j*ATS + ty*2]);
            const u64* hp = reinterpret_cast<const u64*>(&sh[cur][k*64 + tx*4]);
            const u64* hq = reinterpret_cast<const u64*>(&sh[cur][k*64 + 32 + tx*4]);
            u64 h0 = hp[0], h1 = hp[1], h2 = hq[0], h3 = hq[1];
            u64 i0p = pack2(ia.x, ia.x);
            u64 i1p = pack2(ia.y, ia.y);
            fma2(acc[0][0], i0p, h0); fma2(acc[0][1], i0p, h1);
            fma2(acc[0][2], i0p, h2); fma2(acc[0][3], i0p, h3);
            fma2(acc[1][0], i1p, h0); fma2(acc[1][1], i1p, h1);
            fma2(acc[1][2], i1p, h2); fma2(acc[1][3], i1p, h3);
        }
        __syncthreads();
    }
#undef ISSUE_H

    // thread holds rows i0+ty*2+{0,1}, cols c0 + {tx*4..+3, 32+tx*4..+3}
    if (last) {
        float* graph = g_zbuf + GRAPH_OFF;
        float colsum[8];
#pragma unroll
        for (int q = 0; q < 8; ++q) colsum[q] = 0.f;
#pragma unroll
        for (int r = 0; r < 2; ++r) {
            float2 v0 = unpack2(acc[r][0]);
            float2 v1 = unpack2(acc[r][1]);
            float2 v2 = unpack2(acc[r][2]);
            float2 v3 = unpack2(acc[r][3]);
            colsum[0] += fmaxf(v0.x, 0.f); colsum[1] += fmaxf(v0.y, 0.f);
            colsum[2] += fmaxf(v1.x, 0.f); colsum[3] += fmaxf(v1.y, 0.f);
            colsum[4] += fmaxf(v2.x, 0.f); colsum[5] += fmaxf(v2.y, 0.f);
            colsum[6] += fmaxf(v3.x, 0.f); colsum[7] += fmaxf(v3.y, 0.f);
        }
#pragma unroll
        for (int q = 0; q < 8; ++q) {
            int col = (q < 4) ? (tx*4 + q) : (32 + tx*4 + q - 4);
            atomicAdd(&graph[b*Hv + c0 + col], colsum[q]);
        }
    } else {
        // transpose relu through smem (reuse att as st[i][c], stride 68)
        __syncthreads();
        float* st = att;
#pragma unroll
        for (int r = 0; r < 2; ++r) {
            int il = ty*2 + r;
            float2 v0 = unpack2(acc[r][0]);
            float2 v1 = unpack2(acc[r][1]);
            float2 v2 = unpack2(acc[r][2]);
            float2 v3 = unpack2(acc[r][3]);
            st[il*ATS + tx*4 + 0]      = fmaxf(v0.x, 0.f);
            st[il*ATS + tx*4 + 1]      = fmaxf(v0.y, 0.f);
            st[il*ATS + tx*4 + 2]      = fmaxf(v1.x, 0.f);
            st[il*ATS + tx*4 + 3]      = fmaxf(v1.y, 0.f);
            st[il*ATS + 32 + tx*4 + 0] = fmaxf(v2.x, 0.f);
            st[il*ATS + 32 + tx*4 + 1] = fmaxf(v2.y, 0.f);
            st[il*ATS + 32 + tx*4 + 2] = fmaxf(v3.x, 0.f);
            st[il*ATS + 32 + tx*4 + 3] = fmaxf(v3.y, 0.f);
        }
        __syncthreads();
        // thread t: channel ch = t&63, quarter = t>>6 -> 16 rows each
        int ch = t & 63;
        int qt = t >> 6;
        float* dst = &g_xT[(size_t)(c0 + ch)*BN + b*Nv + i0 + qt*16];
#pragma unroll
        for (int q = 0; q < 4; ++q) {
            int i = qt*16 + 4*q;
            float4 o = make_float4(st[(i+0)*ATS + ch], st[(i+1)*ATS + ch],
                                   st[(i+2)*ATS + ch], st[(i+3)*ATS + ch]);
            *reinterpret_cast<float4*>(dst + 4*q) = o;
        }
    }
}

// ---------------------------------------------------------------------------
// K5: fused head. One block per batch element.
// ---------------------------------------------------------------------------
__global__ void k_head(const float* __restrict__ scaffold,
                       const float* __restrict__ W_sc,
                       const float* __restrict__ b_sc,
                       const float* __restrict__ gp_w1,
                       const float* __restrict__ gp_b1,
                       const float* __restrict__ gp_w2,
                       const float* __restrict__ gp_b2,
                       const float* __restrict__ out_w1,
                       const float* __restrict__ out_b1,
                       const float* __restrict__ out_w2,
                       const float* __restrict__ out_b2,
                       float* __restrict__ out)
{
    int b = blockIdx.x, t = threadIdx.x;
    const float* graph = g_zbuf + GRAPH_OFF;
    __shared__ float scaf[Sv];
    __shared__ float grow[Hv];
    __shared__ float sc[Hv];
    __shared__ float g1[128], sp1[128];
    __shared__ float c[128];
    __shared__ float hdn[128];

    if (t < Sv) scaf[t] = scaffold[b*Sv + t];
    grow[t] = graph[b*Hv + t] * (1.0f/Nv);
    __syncthreads();

    {
        float acc = b_sc[t];
#pragma unroll
        for (int k = 0; k < Sv; ++k)
            acc += scaf[k] * W_sc[k*Hv + t];
        sc[t] = acc;
    }
    __syncthreads();

    {
        int col = t & 127;
        const float* src = (t < 128) ? grow : sc;
        float acc = gp_b1[col];
#pragma unroll 4
        for (int k = 0; k < Hv; ++k)
            acc += src[k] * gp_w1[k*128 + col];
        acc = fmaxf(acc, 0.f);
        if (t < 128) g1[col] = acc; else sp1[col] = acc;
    }
    __syncthreads();

    if (t < 128) {
        int col = t & 63;
        const float* src = (t < 64) ? g1 : sp1;
        float acc = gp_b2[col];
#pragma unroll 4
        for (int k = 0; k < 128; ++k)
            acc += src[k] * gp_w2[k*64 + col];
        c[t] = fmaxf(acc, 0.f);
    }
    __syncthreads();

    if (t < 128) {
        float acc = out_b1[t];
#pragma unroll 4
        for (int k = 0; k < 128; ++k)
            acc += c[k] * out_w1[k*128 + t];
        hdn[t] = fmaxf(acc, 0.f);
    }
    __syncthreads();

    if (t < Tv) {
        float acc = out_b2[t];
#pragma unroll 4
        for (int k = 0; k < 128; ++k)
            acc += hdn[k] * out_w2[k*Tv + t];
        out[b*Tv + t] = acc;
    }
}

// ---------------------------------------------------------------------------
extern "C" void kernel_launch(void* const* d_in, const int* in_sizes, int n_in,
                              void* d_out, int out_size)
{
    const float* node_features     = (const float*)d_in[0];
    // d_in[1] = edge_features — unused by the reference
    const int*   adj_matrix        = (const int*)  d_in[2];
    const float* scaffold_features = (const float*)d_in[3];
    const float* W_node            = (const float*)d_in[4];
    const float* b_node            = (const float*)d_in[5];
    const float* gat_W             = (const float*)d_in[6];
    const float* gat_a             = (const float*)d_in[7];
    const float* W_sc              = (const float*)d_in[8];
    const float* b_sc              = (const float*)d_in[9];
    const float* gp_w1             = (const float*)d_in[10];
    const float* gp_b1             = (const float*)d_in[11];
    const float* gp_w2             = (const float*)d_in[12];
    const float* gp_b2             = (const float*)d_in[13];
    const float* out_w1            = (const float*)d_in[14];
    const float* out_b1            = (const float*)d_in[15];
    const float* out_w2            = (const float*)d_in[16];
    const float* out_b2            = (const float*)d_in[17];
    float* out = (float*)d_out;

    void* zp = nullptr;
    cudaGetSymbolAddress(&zp, g_zbuf);
    cudaMemsetAsync(zp, 0, (Lv*2*BN + Bv*Hv)*sizeof(float));

    k_node_proj<<<BN/NP_ROWS, 256>>>(node_features, W_node, b_node);

    for (int l = 0; l < Lv; ++l) {
        dim3 pg(BN/64, Hv/64);                 // 64 x 4 = 256 blocks, 256 thr
        k_gat_proj<<<pg, 256>>>(gat_W + (size_t)l*Hv*Hv,
                                gat_a + (size_t)l*2*Hv, l);
        dim3 ag(Nv/64, Hv/64, Bv);             // 2 x 4 x 32 = 256 blocks, 256 thr
        k_gat_agg<<<ag, 256>>>(adj_matrix, l, l == Lv-1);
    }

    k_head<<<Bv, 256>>>(scaffold_features, W_sc, b_sc,
                        gp_w1, gp_b1, gp_w2, gp_b2,
                        out_w1, out_b1, out_w2, out_b2, out);
}

// round 10
// speedup vs baseline: 1.2552x; 1.2536x over previous
#include <cuda_runtime.h>
#include <cuda_bf16.h>
#include <cstdint>

// Problem constants
#define Bv   32
#define Nv   128
#define Fv   78
#define Hv   256
#define Sv   20
#define Tv   13
#define Lv   3
#define ALPHA 0.2f
#define NEG_INF -9000000000000000.0f

#define BN (Bv*Nv)          // 4096 rows

// Scratch (device globals; no allocation allowed)
__device__ float g_xT[Hv*BN];                 // activations TRANSPOSED [c][row]
__device__ float g_h[BN*Hv];                  // projected h, normal [row][c]
__device__ float g_zbuf[Lv*2*BN + Bv*Hv];     // s1/s2 per layer + graph accum

#define GRAPH_OFF (Lv*2*BN)

// ---------------------------------------------------------------------------
// packed fp32x2 helpers
// ---------------------------------------------------------------------------
typedef unsigned long long u64;

__device__ __forceinline__ void fma2(u64& d, u64 a, u64 b) {
    asm("fma.rn.f32x2 %0, %1, %2, %0;" : "+l"(d) : "l"(a), "l"(b));
}
__device__ __forceinline__ u64 add2(u64 a, u64 b) {
    u64 d;
    asm("add.rn.f32x2 %0, %1, %2;" : "=l"(d) : "l"(a), "l"(b));
    return d;
}
__device__ __forceinline__ u64 pack2(float lo, float hi) {
    u64 r;
    asm("mov.b64 %0, {%1, %2};" : "=l"(r) : "f"(lo), "f"(hi));
    return r;
}
__device__ __forceinline__ float2 unpack2(u64 p) {
    float lo, hi;
    asm("mov.b64 {%0, %1}, %2;" : "=f"(lo), "=f"(hi) : "l"(p));
    return make_float2(lo, hi);
}

// cp.async helpers
__device__ __forceinline__ void cp16(uint32_t s, const void* g) {
    asm volatile("cp.async.ca.shared.global [%0], [%1], 16;" :: "r"(s), "l"(g));
}
#define CP_COMMIT() asm volatile("cp.async.commit_group;")
#define CP_WAIT1()  asm volatile("cp.async.wait_group 1;")
#define CP_WAIT0()  asm volatile("cp.async.wait_group 0;")

// ---------------------------------------------------------------------------
// K1: x = node_features @ W_node + b_node -> g_xT (transposed)
// ---------------------------------------------------------------------------
#define NP_ROWS 8
__global__ void k_node_proj(const float* __restrict__ nf,
                            const float* __restrict__ W,
                            const float* __restrict__ bias)
{
    int row0 = blockIdx.x * NP_ROWS;
    int j    = threadIdx.x;

    __shared__ __align__(16) float sf[Fv * NP_ROWS];   // [f][r]
    __shared__ float st[NP_ROWS * 257];                // transpose tile

    for (int idx = j; idx < Fv*NP_ROWS; idx += 256) {
        int f = idx >> 3, r = idx & 7;
        sf[idx] = nf[(row0 + r)*Fv + f];
    }
    __syncthreads();

    float bj = bias[j];
    float acc[NP_ROWS];
#pragma unroll
    for (int r = 0; r < NP_ROWS; ++r) acc[r] = bj;

#pragma unroll 6
    for (int f = 0; f < Fv; ++f) {
        float w = W[f*Hv + j];
        const float4* xp = reinterpret_cast<const float4*>(&sf[f*NP_ROWS]);
        float4 xa = xp[0], xb = xp[1];
        acc[0] += xa.x * w;  acc[1] += xa.y * w;
        acc[2] += xa.z * w;  acc[3] += xa.w * w;
        acc[4] += xb.x * w;  acc[5] += xb.y * w;
        acc[6] += xb.z * w;  acc[7] += xb.w * w;
    }

#pragma unroll
    for (int r = 0; r < NP_ROWS; ++r)
        st[r*257 + j] = acc[r];
    __syncthreads();
    int r  = j & 7;
    int cb = j >> 3;          // 0..31
#pragma unroll
    for (int p = 0; p < 8; ++p) {
        int c = cb + 32*p;
        g_xT[(size_t)c*BN + row0 + r] = st[r*257 + c];
    }
}

// ---------------------------------------------------------------------------
// K2: h = x @ gat_W[l] + partial scores.
// 256 threads = 2 groups x 128; tile 64x64; thread = 4 rows x 8 cols (f32x2);
// groups split each staged K-chunk (kk 0-15 vs 16-31); smem f32x2 reduction.
// ---------------------------------------------------------------------------
#define KCp 32
__global__ void __launch_bounds__(256)
k_gat_proj(const float* __restrict__ W,   // [256,256]
           const float* __restrict__ a,   // [512]
           int layer)
{
    const int row0 = blockIdx.x * 64;
    const int c0   = blockIdx.y * 64;
    const int t  = threadIdx.x;           // 0..255
    const int g  = t >> 7;                // k-half group
    const int tl = t & 127;
    const int tx = tl & 7, ty = tl >> 3;  // 8 col-groups x 16 row-groups

    float* s1 = g_zbuf + layer*2*BN;
    float* s2 = s1 + BN;

    // sbuf: sx = floats [0,4096) (2 bufs x 32k x 64 rows), sw = [4096,8192)
    __shared__ __align__(16) float sbuf[8192];
    float* sx = sbuf;
    float* sw = sbuf + 4096;
    const uint32_t sba = (uint32_t)__cvta_generic_to_shared(sbuf);
    const float* xT = g_xT;

    // staging: group 0 threads load x pieces, group 1 threads load w pieces
#define ISSUE_CHUNK(kc, buf)                                                   \
    {                                                                          \
        _Pragma("unroll")                                                      \
        for (int m = 0; m < 4; ++m) {                                          \
            int idx = tl + 128*m;                                              \
            int k = idx >> 4, f = idx & 15;                                    \
            if (g == 0) {                                                      \
                uint32_t off = ((buf)*2048 + k*64 + f*4)*4;                    \
                cp16(sba + off, &xT[(size_t)((kc)+k)*BN + row0 + f*4]);        \
            } else {                                                           \
                uint32_t off = 16384u + ((buf)*2048 + k*64 + f*4)*4;           \
                cp16(sba + off, &W[((kc)+k)*Hv + c0 + f*4]);                   \
            }                                                                  \
        }                                                                      \
        CP_COMMIT();                                                           \
    }

    u64 acc[4][4];
#pragma unroll
    for (int r = 0; r < 4; ++r)
#pragma unroll
        for (int p = 0; p < 4; ++p) acc[r][p] = pack2(0.f, 0.f);

    ISSUE_CHUNK(0, 0);

    const int NCH = Hv / KCp;      // 8
#pragma unroll
    for (int c = 0; c < NCH; ++c) {
        const int cur = c & 1;
        if (c + 1 < NCH) {
            ISSUE_CHUNK((c+1)*KCp, (c+1)&1);
            CP_WAIT1();
        } else {
            CP_WAIT0();
        }
        __syncthreads();

#pragma unroll 8
        for (int kk = 0; kk < 16; ++kk) {
            int k = g*16 + kk;
            float4 xa = *reinterpret_cast<const float4*>(&sx[cur*2048 + k*64 + ty*4]);
            const u64* wp = reinterpret_cast<const u64*>(&sw[cur*2048 + k*64 + tx*4]);
            const u64* wq = reinterpret_cast<const u64*>(&sw[cur*2048 + k*64 + 32 + tx*4]);
            u64 w0 = wp[0], w1 = wp[1], w2 = wq[0], w3 = wq[1];
            u64 x0 = pack2(xa.x, xa.x);
            u64 x1 = pack2(xa.y, xa.y);
            u64 x2 = pack2(xa.z, xa.z);
            u64 x3 = pack2(xa.w, xa.w);
            fma2(acc[0][0], x0, w0); fma2(acc[0][1], x0, w1);
            fma2(acc[0][2], x0, w2); fma2(acc[0][3], x0, w3);
            fma2(acc[1][0], x1, w0); fma2(acc[1][1], x1, w1);
            fma2(acc[1][2], x1, w2); fma2(acc[1][3], x1, w3);
            fma2(acc[2][0], x2, w0); fma2(acc[2][1], x2, w1);
            fma2(acc[2][2], x2, w2); fma2(acc[2][3], x2, w3);
            fma2(acc[3][0], x3, w0); fma2(acc[3][1], x3, w1);
            fma2(acc[3][2], x3, w2); fma2(acc[3][3], x3, w3);
        }
        __syncthreads();
    }
#undef ISSUE_CHUNK

    // split-K reduction through smem (reuse sx region: 2048 u64 = 16KB)
    u64* red = reinterpret_cast<u64*>(sbuf);
    if (g == 1) {
#pragma unroll
        for (int r = 0; r < 4; ++r)
#pragma unroll
            for (int p = 0; p < 4; ++p)
                red[(r*4 + p)*128 + tl] = acc[r][p];
    }
    __syncthreads();
    if (g == 0) {
#pragma unroll
        for (int r = 0; r < 4; ++r)
#pragma unroll
            for (int p = 0; p < 4; ++p)
                acc[r][p] = add2(acc[r][p], red[(r*4 + p)*128 + tl]);

        // epilogue: store h, reduce scores across the 8 tx lanes
        float4 a1a = *reinterpret_cast<const float4*>(&a[c0 + tx*4]);
        float4 a1b = *reinterpret_cast<const float4*>(&a[c0 + 32 + tx*4]);
        float4 a2a = *reinterpret_cast<const float4*>(&a[Hv + c0 + tx*4]);
        float4 a2b = *reinterpret_cast<const float4*>(&a[Hv + c0 + 32 + tx*4]);

#pragma unroll
        for (int r = 0; r < 4; ++r) {
            int row = row0 + ty*4 + r;
            float2 v0 = unpack2(acc[r][0]);
            float2 v1 = unpack2(acc[r][1]);
            float2 v2 = unpack2(acc[r][2]);
            float2 v3 = unpack2(acc[r][3]);
            *reinterpret_cast<float4*>(&g_h[(size_t)row*Hv + c0 + tx*4]) =
                make_float4(v0.x, v0.y, v1.x, v1.y);
            *reinterpret_cast<float4*>(&g_h[(size_t)row*Hv + c0 + 32 + tx*4]) =
                make_float4(v2.x, v2.y, v3.x, v3.y);

            float p1 = v0.x*a1a.x + v0.y*a1a.y + v1.x*a1a.z + v1.y*a1a.w
                     + v2.x*a1b.x + v2.y*a1b.y + v3.x*a1b.z + v3.y*a1b.w;
            float p2 = v0.x*a2a.x + v0.y*a2a.y + v1.x*a2a.z + v1.y*a2a.w
                     + v2.x*a2b.x + v2.y*a2b.y + v3.x*a2b.z + v3.y*a2b.w;
#pragma unroll
            for (int off = 4; off > 0; off >>= 1) {
                p1 += __shfl_xor_sync(0xffffffffu, p1, off);
                p2 += __shfl_xor_sync(0xffffffffu, p2, off);
            }
            if (tx == 0) {
                atomicAdd(&s1[row], p1);
                atomicAdd(&s2[row], p2);
            }
        }
    }
}

// ---------------------------------------------------------------------------
// K3: softmax attention + aggregation (+ fused mean on last layer)
// 256 threads = 2 groups x 128; tile 64 att-rows x 64 channels;
// thread = 4 rows x 8 cols (f32x2); groups split each staged j-chunk.
// ---------------------------------------------------------------------------
#define JCa 32
#define ATS 68
__global__ void __launch_bounds__(256)
k_gat_agg(const int* __restrict__ adj, int layer, int last)
{
    const int b  = blockIdx.z;
    const int i0 = blockIdx.x * 64;
    const int c0 = blockIdx.y * 64;
    const int t  = threadIdx.x;            // 0..255
    const int g  = t >> 7;                 // j-half group
    const int tl = t & 127;
    const int tx = tl & 7, ty = tl >> 3;
    const int lane = t & 31, warp = t >> 5;

    const float* s1 = g_zbuf + layer*2*BN;
    const float* s2 = s1 + BN;

    __shared__ __align__(16) float s2_sh[Nv];
    __shared__ __align__(16) float att[Nv * ATS];     // [j][i_local]; reused as st
    __shared__ __align__(16) float shb[2][JCa*64];    // h chunks; reused for reduction

    const uint32_t shba = (uint32_t)__cvta_generic_to_shared(shb);
    const float* hb = g_h + (size_t)b*Nv*Hv;

#define ISSUE_H(jc, buf)                                                       \
    {                                                                          \
        _Pragma("unroll")                                                      \
        for (int m = 0; m < 2; ++m) {                                          \
            int idx = t + 256*m;                                               \
            int k = idx >> 4, f = idx & 15;                                    \
            uint32_t off = ((buf)*2048 + k*64 + f*4)*4;                        \
            cp16(shba + off, &hb[(size_t)((jc)+k)*Hv + c0 + f*4]);             \
        }                                                                      \
        CP_COMMIT();                                                           \
    }

    ISSUE_H(0, 0);       // overlap with softmax

    if (t < Nv) s2_sh[t] = s2[b*Nv + t];
    __syncthreads();

    // softmax: 8 rows per warp (8 warps x 8 = 64 rows); int4 adj loads
#pragma unroll
    for (int rr = 0; rr < 8; ++rr) {
        int il = warp*8 + rr;
        int i  = i0 + il;
        float s1i = s1[b*Nv + i];
        const int* adj_row = adj + (size_t)(b*Nv + i)*Nv;
        int4   am  = *reinterpret_cast<const int4*>(&adj_row[lane*4]);
        float4 s2v = *reinterpret_cast<const float4*>(&s2_sh[lane*4]);
        float e[4];
        {
            float v0 = s1i + s2v.x, v1 = s1i + s2v.y;
            float v2 = s1i + s2v.z, v3 = s1i + s2v.w;
            v0 = (v0 > 0.f) ? v0 : ALPHA*v0;  v1 = (v1 > 0.f) ? v1 : ALPHA*v1;
            v2 = (v2 > 0.f) ? v2 : ALPHA*v2;  v3 = (v3 > 0.f) ? v3 : ALPHA*v3;
            e[0] = (am.x > 0) ? v0 : NEG_INF;
            e[1] = (am.y > 0) ? v1 : NEG_INF;
            e[2] = (am.z > 0) ? v2 : NEG_INF;
            e[3] = (am.w > 0) ? v3 : NEG_INF;
        }
        float mx = fmaxf(fmaxf(e[0], e[1]), fmaxf(e[2], e[3]));
#pragma unroll
        for (int off = 16; off > 0; off >>= 1)
            mx = fmaxf(mx, __shfl_xor_sync(0xffffffffu, mx, off));
        float sum = 0.f;
#pragma unroll
        for (int q = 0; q < 4; ++q) { e[q] = __expf(e[q] - mx); sum += e[q]; }
#pragma unroll
        for (int off = 16; off > 0; off >>= 1)
            sum += __shfl_xor_sync(0xffffffffu, sum, off);
        float inv = 1.f / sum;
#pragma unroll
        for (int q = 0; q < 4; ++q)
            att[(lane*4 + q)*ATS + il] = e[q] * inv;
    }

    u64 acc[4][4];
#pragma unroll
    for (int r = 0; r < 4; ++r)
#pragma unroll
        for (int p = 0; p < 4; ++p) acc[r][p] = pack2(0.f, 0.f);

    const int NJC = Nv / JCa;      // 4
#pragma unroll
    for (int c = 0; c < NJC; ++c) {
        const int cur = c & 1;
        if (c + 1 < NJC) {
            ISSUE_H((c+1)*JCa, (c+1)&1);
            CP_WAIT1();
        } else {
            CP_WAIT0();
        }
        __syncthreads();

#pragma unroll 8
        for (int kk = 0; kk < 16; ++kk) {
            int kc = g*16 + kk;           // index within chunk
            int j  = c*JCa + kc;          // global j
            float4 ia = *reinterpret_cast<const float4*>(&att[j*ATS + ty*4]);
            const u64* hp = reinterpret_cast<const u64*>(&shb[cur][kc*64 + tx*4]);
            const u64* hq = reinterpret_cast<const u64*>(&shb[cur][kc*64 + 32 + tx*4]);
            u64 h0 = hp[0], h1 = hp[1], h2 = hq[0], h3 = hq[1];
            u64 i0p = pack2(ia.x, ia.x);
            u64 i1p = pack2(ia.y, ia.y);
            u64 i2p = pack2(ia.z, ia.z);
            u64 i3p = pack2(ia.w, ia.w);
            fma2(acc[0][0], i0p, h0); fma2(acc[0][1], i0p, h1);
            fma2(acc[0][2], i0p, h2); fma2(acc[0][3], i0p, h3);
            fma2(acc[1][0], i1p, h0); fma2(acc[1][1], i1p, h1);
            fma2(acc[1][2], i1p, h2); fma2(acc[1][3], i1p, h3);
            fma2(acc[2][0], i2p, h0); fma2(acc[2][1], i2p, h1);
            fma2(acc[2][2], i2p, h2); fma2(acc[2][3], i2p, h3);
            fma2(acc[3][0], i3p, h0); fma2(acc[3][1], i3p, h1);
            fma2(acc[3][2], i3p, h2); fma2(acc[3][3], i3p, h3);
        }
        __syncthreads();
    }
#undef ISSUE_H

    // split-j reduction through smem (reuse shb: 2048 u64 = 16KB)
    u64* red = reinterpret_cast<u64*>(shb);
    if (g == 1) {
#pragma unroll
        for (int r = 0; r < 4; ++r)
#pragma unroll
            for (int p = 0; p < 4; ++p)
                red[(r*4 + p)*128 + tl] = acc[r][p];
    }
    __syncthreads();

    if (last) {
        if (g == 0) {
            float* graph = g_zbuf + GRAPH_OFF;
            float colsum[8];
#pragma unroll
            for (int q = 0; q < 8; ++q) colsum[q] = 0.f;
#pragma unroll
            for (int r = 0; r < 4; ++r) {
#pragma unroll
                for (int p = 0; p < 4; ++p)
                    acc[r][p] = add2(acc[r][p], red[(r*4 + p)*128 + tl]);
                float2 v0 = unpack2(acc[r][0]);
                float2 v1 = unpack2(acc[r][1]);
                float2 v2 = unpack2(acc[r][2]);
                float2 v3 = unpack2(acc[r][3]);
                colsum[0] += fmaxf(v0.x, 0.f); colsum[1] += fmaxf(v0.y, 0.f);
                colsum[2] += fmaxf(v1.x, 0.f); colsum[3] += fmaxf(v1.y, 0.f);
                colsum[4] += fmaxf(v2.x, 0.f); colsum[5] += fmaxf(v2.y, 0.f);
                colsum[6] += fmaxf(v3.x, 0.f); colsum[7] += fmaxf(v3.y, 0.f);
            }
#pragma unroll
            for (int q = 0; q < 8; ++q) {
                int col = (q < 4) ? (tx*4 + q) : (32 + tx*4 + q - 4);
                atomicAdd(&graph[b*Hv + c0 + col], colsum[q]);
            }
        }
    } else {
        // group 0 reduces + writes st[i][c] (att reuse); all 256 store to g_xT
        float* st = att;
        if (g == 0) {
#pragma unroll
            for (int r = 0; r < 4; ++r) {
#pragma unroll
                for (int p = 0; p < 4; ++p)
                    acc[r][p] = add2(acc[r][p], red[(r*4 + p)*128 + tl]);
                int il = ty*4 + r;
                float2 v0 = unpack2(acc[r][0]);
                float2 v1 = unpack2(acc[r][1]);
                float2 v2 = unpack2(acc[r][2]);
                float2 v3 = unpack2(acc[r][3]);
                st[il*ATS + tx*4 + 0]      = fmaxf(v0.x, 0.f);
                st[il*ATS + tx*4 + 1]      = fmaxf(v0.y, 0.f);
                st[il*ATS + tx*4 + 2]      = fmaxf(v1.x, 0.f);
                st[il*ATS + tx*4 + 3]      = fmaxf(v1.y, 0.f);
                st[il*ATS + 32 + tx*4 + 0] = fmaxf(v2.x, 0.f);
                st[il*ATS + 32 + tx*4 + 1] = fmaxf(v2.y, 0.f);
                st[il*ATS + 32 + tx*4 + 2] = fmaxf(v3.x, 0.f);
                st[il*ATS + 32 + tx*4 + 3] = fmaxf(v3.y, 0.f);
            }
        }
        __syncthreads();
        // thread t: channel ch = t&63, quarter qt = t>>6 -> 16 rows each
        int ch = t & 63;
        int qt = t >> 6;
        float* dst = &g_xT[(size_t)(c0 + ch)*BN + b*Nv + i0 + qt*16];
#pragma unroll
        for (int q = 0; q < 4; ++q) {
            int i = qt*16 + 4*q;
            float4 o = make_float4(st[(i+0)*ATS + ch], st[(i+1)*ATS + ch],
                                   st[(i+2)*ATS + ch], st[(i+3)*ATS + ch]);
            *reinterpret_cast<float4*>(dst + 4*q) = o;
        }
    }
}

// ---------------------------------------------------------------------------
// K5: fused head. One block per batch element.
// ---------------------------------------------------------------------------
__global__ void k_head(const float* __restrict__ scaffold,
                       const float* __restrict__ W_sc,
                       const float* __restrict__ b_sc,
                       const float* __restrict__ gp_w1,
                       const float* __restrict__ gp_b1,
                       const float* __restrict__ gp_w2,
                       const float* __restrict__ gp_b2,
                       const float* __restrict__ out_w1,
                       const float* __restrict__ out_b1,
                       const float* __restrict__ out_w2,
                       const float* __restrict__ out_b2,
                       float* __restrict__ out)
{
    int b = blockIdx.x, t = threadIdx.x;
    const float* graph = g_zbuf + GRAPH_OFF;
    __shared__ float scaf[Sv];
    __shared__ float grow[Hv];
    __shared__ float sc[Hv];
    __shared__ float g1[128], sp1[128];
    __shared__ float c[128];
    __shared__ float hdn[128];

    if (t < Sv) scaf[t] = scaffold[b*Sv + t];
    grow[t] = graph[b*Hv + t] * (1.0f/Nv);
    __syncthreads();

    {
        float acc = b_sc[t];
#pragma unroll
        for (int k = 0; k < Sv; ++k)
            acc += scaf[k] * W_sc[k*Hv + t];
        sc[t] = acc;
    }
    __syncthreads();

    {
        int col = t & 127;
        const float* src = (t < 128) ? grow : sc;
        float acc = gp_b1[col];
#pragma unroll 4
        for (int k = 0; k < Hv; ++k)
            acc += src[k] * gp_w1[k*128 + col];
        acc = fmaxf(acc, 0.f);
        if (t < 128) g1[col] = acc; else sp1[col] = acc;
    }
    __syncthreads();

    if (t < 128) {
        int col = t & 63;
        const float* src = (t < 64) ? g1 : sp1;
        float acc = gp_b2[col];
#pragma unroll 4
        for (int k = 0; k < 128; ++k)
            acc += src[k] * gp_w2[k*64 + col];
        c[t] = fmaxf(acc, 0.f);
    }
    __syncthreads();

    if (t < 128) {
        float acc = out_b1[t];
#pragma unroll 4
        for (int k = 0; k < 128; ++k)
            acc += c[k] * out_w1[k*128 + t];
        hdn[t] = fmaxf(acc, 0.f);
    }
    __syncthreads();

    if (t < Tv) {
        float acc = out_b2[t];
#pragma unroll 4
        for (int k = 0; k < 128; ++k)
            acc += hdn[k] * out_w2[k*Tv + t];
        out[b*Tv + t] = acc;
    }
}

// ---------------------------------------------------------------------------
extern "C" void kernel_launch(void* const* d_in, const int* in_sizes, int n_in,
                              void* d_out, int out_size)
{
    const float* node_features     = (const float*)d_in[0];
    // d_in[1] = edge_features — unused by the reference
    const int*   adj_matrix        = (const int*)  d_in[2];
    const float* scaffold_features = (const float*)d_in[3];
    const float* W_node            = (const float*)d_in[4];
    const float* b_node            = (const float*)d_in[5];
    const float* gat_W             = (const float*)d_in[6];
    const float* gat_a             = (const float*)d_in[7];
    const float* W_sc              = (const float*)d_in[8];
    const float* b_sc              = (const float*)d_in[9];
    const float* gp_w1             = (const float*)d_in[10];
    const float* gp_b1             = (const float*)d_in[11];
    const float* gp_w2             = (const float*)d_in[12];
    const float* gp_b2             = (const float*)d_in[13];
    const float* out_w1            = (const float*)d_in[14];
    const float* out_b1            = (const float*)d_in[15];
    const float* out_w2            = (const float*)d_in[16];
    const float* out_b2            = (const float*)d_in[17];
    float* out = (float*)d_out;

    void* zp = nullptr;
    cudaGetSymbolAddress(&zp, g_zbuf);
    cudaMemsetAsync(zp, 0, (Lv*2*BN + Bv*Hv)*sizeof(float));

    k_node_proj<<<BN/NP_ROWS, 256>>>(node_features, W_node, b_node);

    for (int l = 0; l < Lv; ++l) {
        dim3 pg(BN/64, Hv/64);                 // 64 x 4 = 256 blocks, 256 thr
        k_gat_proj<<<pg, 256>>>(gat_W + (size_t)l*Hv*Hv,
                                gat_a + (size_t)l*2*Hv, l);
        dim3 ag(Nv/64, Hv/64, Bv);             // 2 x 4 x 32 = 256 blocks, 256 thr
        k_gat_agg<<<ag, 256>>>(adj_matrix, l, l == Lv-1);
    }

    k_head<<<Bv, 256>>>(scaffold_features, W_sc, b_sc,
                        gp_w1, gp_b1, gp_w2, gp_b2,
                        out_w1, out_b1, out_w2, out_b2, out);
}

// round 11
// speedup vs baseline: 1.2887x; 1.0266x over previous
#include <cuda_runtime.h>
#include <cuda_bf16.h>
#include <cstdint>

// Problem constants
#define Bv   32
#define Nv   128
#define Fv   78
#define Hv   256
#define Sv   20
#define Tv   13
#define Lv   3
#define ALPHA 0.2f
#define NEG_INF -9000000000000000.0f

#define BN (Bv*Nv)          // 4096 rows

// Scratch (device globals; no allocation allowed)
__device__ float g_xhi[(size_t)Hv*BN];        // x transposed [c][row], tf32 hi
__device__ float g_xlo[(size_t)Hv*BN];        // x transposed [c][row], tf32 lo
__device__ float g_h[(size_t)BN*Hv];          // projected h, fp32 [row][c]
__device__ float g_whi[Lv*Hv*Hv];             // gat_W tf32 hi (all layers)
__device__ float g_wlo[Lv*Hv*Hv];             // gat_W tf32 lo
__device__ float g_zbuf[Lv*2*BN + Bv*Hv];     // s1/s2 per layer + graph accum

#define GRAPH_OFF (Lv*2*BN)

// ---------------------------------------------------------------------------
// helpers
// ---------------------------------------------------------------------------
typedef unsigned long long u64;

__device__ __forceinline__ void fma2(u64& d, u64 a, u64 b) {
    asm("fma.rn.f32x2 %0, %1, %2, %0;" : "+l"(d) : "l"(a), "l"(b));
}
__device__ __forceinline__ u64 add2(u64 a, u64 b) {
    u64 d;
    asm("add.rn.f32x2 %0, %1, %2;" : "=l"(d) : "l"(a), "l"(b));
    return d;
}
__device__ __forceinline__ u64 pack2(float lo, float hi) {
    u64 r;
    asm("mov.b64 %0, {%1, %2};" : "=l"(r) : "f"(lo), "f"(hi));
    return r;
}
__device__ __forceinline__ float2 unpack2(u64 p) {
    float lo, hi;
    asm("mov.b64 {%0, %1}, %2;" : "=f"(lo), "=f"(hi) : "l"(p));
    return make_float2(lo, hi);
}
__device__ __forceinline__ void tf32split(float v, float& hi, float& lo) {
    uint32_t u;
    asm("cvt.rna.tf32.f32 %0, %1;" : "=r"(u) : "f"(v));
    hi = __uint_as_float(u);
    float r = v - hi;
    asm("cvt.rna.tf32.f32 %0, %1;" : "=r"(u) : "f"(r));
    lo = __uint_as_float(u);
}

// cp.async helpers
__device__ __forceinline__ void cp16(uint32_t s, const void* g) {
    asm volatile("cp.async.ca.shared.global [%0], [%1], 16;" :: "r"(s), "l"(g));
}
#define CP_COMMIT() asm volatile("cp.async.commit_group;")
#define CP_WAIT1()  asm volatile("cp.async.wait_group 1;")
#define CP_WAIT0()  asm volatile("cp.async.wait_group 0;")

// tf32 mma m16n8k8 (A row-major, B col-major, fp32 accum)
#define MMA_TF32(C, A, B0, B1)                                                 \
    asm("mma.sync.aligned.m16n8k8.row.col.f32.tf32.tf32.f32 "                  \
        "{%0,%1,%2,%3}, {%4,%5,%6,%7}, {%8,%9}, {%0,%1,%2,%3};"                \
        : "+f"((C)[0]), "+f"((C)[1]), "+f"((C)[2]), "+f"((C)[3])               \
        : "r"((A)[0]), "r"((A)[1]), "r"((A)[2]), "r"((A)[3]),                  \
          "r"(B0), "r"(B1))

// ---------------------------------------------------------------------------
// K0: split gat_W into tf32 hi/lo for all layers
// ---------------------------------------------------------------------------
__global__ void k_split_w(const float* __restrict__ gat_W)
{
    int idx = blockIdx.x*256 + threadIdx.x;   // 0 .. 3*65536-1
    float v = gat_W[idx];
    float hi, lo;
    tf32split(v, hi, lo);
    g_whi[idx] = hi;
    g_wlo[idx] = lo;
}

// ---------------------------------------------------------------------------
// K1: x = node_features @ W_node + b_node -> g_xhi/g_xlo (transposed, split)
// ---------------------------------------------------------------------------
#define NP_ROWS 8
__global__ void k_node_proj(const float* __restrict__ nf,
                            const float* __restrict__ W,
                            const float* __restrict__ bias)
{
    int row0 = blockIdx.x * NP_ROWS;
    int j    = threadIdx.x;

    __shared__ __align__(16) float sf[Fv * NP_ROWS];   // [f][r]
    __shared__ float st[NP_ROWS * 257];                // transpose tile

    for (int idx = j; idx < Fv*NP_ROWS; idx += 256) {
        int f = idx >> 3, r = idx & 7;
        sf[idx] = nf[(row0 + r)*Fv + f];
    }
    __syncthreads();

    float bj = bias[j];
    float acc[NP_ROWS];
#pragma unroll
    for (int r = 0; r < NP_ROWS; ++r) acc[r] = bj;

#pragma unroll 6
    for (int f = 0; f < Fv; ++f) {
        float w = W[f*Hv + j];
        const float4* xp = reinterpret_cast<const float4*>(&sf[f*NP_ROWS]);
        float4 xa = xp[0], xb = xp[1];
        acc[0] += xa.x * w;  acc[1] += xa.y * w;
        acc[2] += xa.z * w;  acc[3] += xa.w * w;
        acc[4] += xb.x * w;  acc[5] += xb.y * w;
        acc[6] += xb.z * w;  acc[7] += xb.w * w;
    }

#pragma unroll
    for (int r = 0; r < NP_ROWS; ++r)
        st[r*257 + j] = acc[r];
    __syncthreads();
    int r  = j & 7;
    int cb = j >> 3;          // 0..31
#pragma unroll
    for (int p = 0; p < 8; ++p) {
        int c = cb + 32*p;
        float v = st[r*257 + c];
        float hi, lo;
        tf32split(v, hi, lo);
        g_xhi[(size_t)c*BN + row0 + r] = hi;
        g_xlo[(size_t)c*BN + row0 + r] = lo;
    }
}

// ---------------------------------------------------------------------------
// K2: h = x @ gat_W[l] via tf32 mma.sync (3-pass split) + partial scores.
// 128 threads = 4 warps; block tile 64 rows x 64 cols; warp tile 32x32.
// ---------------------------------------------------------------------------
#define PKC  16            // k per staged chunk
#define PSTR 72            // padded row length (conflict-free fragments)
__global__ void __launch_bounds__(128)
k_gat_proj(const float* __restrict__ a,   // [512] (a1 | a2)
           int layer)
{
    const int row0 = blockIdx.x * 64;
    const int c0   = blockIdx.y * 64;
    const int t    = threadIdx.x;
    const int w    = t >> 5, lane = t & 31;
    const int g    = lane >> 2, tid = lane & 3;
    const int row0w = (w & 1) * 32;
    const int col0w = (w >> 1) * 32;

    const float* xhi = g_xhi;
    const float* xlo = g_xlo;
    const float* whi = g_whi + (size_t)layer*Hv*Hv;
    const float* wlo = g_wlo + (size_t)layer*Hv*Hv;
    float* s1 = g_zbuf + layer*2*BN;
    float* s2 = s1 + BN;

    // smem: [buf][arr][k][PSTR]; arr: 0=xhi 1=xlo 2=whi 3=wlo
    __shared__ __align__(16) float sb[2][4][PKC*PSTR];
    const uint32_t sba = (uint32_t)__cvta_generic_to_shared(sb);

    // stage one chunk: 4 arrays x 16k x 16 float4-pieces = 1024 cp16 / 128 thr
#define PISSUE(kc, buf)                                                        \
    {                                                                          \
        _Pragma("unroll")                                                      \
        for (int m = 0; m < 8; ++m) {                                          \
            const int arr = m >> 1;                                            \
            int sub = t + 128*(m & 1);      /* 0..255 */                       \
            int k = sub >> 4, f = sub & 15;                                    \
            uint32_t doff = sba + (((buf)*4 + arr)*(PKC*PSTR) + k*PSTR + f*4)*4; \
            const float* src;                                                  \
            if (arr == 0)      src = &xhi[(size_t)((kc)+k)*BN + row0 + f*4];   \
            else if (arr == 1) src = &xlo[(size_t)((kc)+k)*BN + row0 + f*4];   \
            else if (arr == 2) src = &whi[((kc)+k)*Hv + c0 + f*4];             \
            else               src = &wlo[((kc)+k)*Hv + c0 + f*4];             \
            cp16(doff, src);                                                   \
        }                                                                      \
        CP_COMMIT();                                                           \
    }

    float cacc[2][4][4];
#pragma unroll
    for (int mt = 0; mt < 2; ++mt)
#pragma unroll
        for (int nt = 0; nt < 4; ++nt)
#pragma unroll
            for (int q = 0; q < 4; ++q) cacc[mt][nt][q] = 0.f;

    PISSUE(0, 0);

    const int NCH = Hv / PKC;      // 16
#pragma unroll 4
    for (int c = 0; c < NCH; ++c) {
        const int cur = c & 1;
        if (c + 1 < NCH) {
            PISSUE((c+1)*PKC, (c+1)&1);
            CP_WAIT1();
        } else {
            CP_WAIT0();
        }
        __syncthreads();

        const float* sxh = sb[cur][0];
        const float* sxl = sb[cur][1];
        const float* swh = sb[cur][2];
        const float* swl = sb[cur][3];

#pragma unroll
        for (int ks = 0; ks < PKC; ks += 8) {
            uint32_t ah[2][4], al[2][4];
#pragma unroll
            for (int mt = 0; mt < 2; ++mt) {
                int rb = row0w + mt*16 + g;
                ah[mt][0] = __float_as_uint(sxh[(ks+tid)*PSTR + rb]);
                ah[mt][1] = __float_as_uint(sxh[(ks+tid)*PSTR + rb + 8]);
                ah[mt][2] = __float_as_uint(sxh[(ks+tid+4)*PSTR + rb]);
                ah[mt][3] = __float_as_uint(sxh[(ks+tid+4)*PSTR + rb + 8]);
                al[mt][0] = __float_as_uint(sxl[(ks+tid)*PSTR + rb]);
                al[mt][1] = __float_as_uint(sxl[(ks+tid)*PSTR + rb + 8]);
                al[mt][2] = __float_as_uint(sxl[(ks+tid+4)*PSTR + rb]);
                al[mt][3] = __float_as_uint(sxl[(ks+tid+4)*PSTR + rb + 8]);
            }
#pragma unroll
            for (int nt = 0; nt < 4; ++nt) {
                int cb = col0w + nt*8 + g;
                uint32_t bh0 = __float_as_uint(swh[(ks+tid)*PSTR + cb]);
                uint32_t bh1 = __float_as_uint(swh[(ks+tid+4)*PSTR + cb]);
                uint32_t bl0 = __float_as_uint(swl[(ks+tid)*PSTR + cb]);
                uint32_t bl1 = __float_as_uint(swl[(ks+tid+4)*PSTR + cb]);
#pragma unroll
                for (int mt = 0; mt < 2; ++mt) {
                    MMA_TF32(cacc[mt][nt], ah[mt], bh0, bh1);   // hi*hi
                    MMA_TF32(cacc[mt][nt], ah[mt], bl0, bl1);   // hi*lo
                    MMA_TF32(cacc[mt][nt], al[mt], bh0, bh1);   // lo*hi
                }
            }
        }
        __syncthreads();
    }
#undef PISSUE

    // epilogue: store h (fp32), partial scores via quad-reduce + atomics
    float2 a1v[4], a2v[4];
#pragma unroll
    for (int nt = 0; nt < 4; ++nt) {
        a1v[nt] = *reinterpret_cast<const float2*>(&a[c0 + col0w + nt*8 + 2*tid]);
        a2v[nt] = *reinterpret_cast<const float2*>(&a[Hv + c0 + col0w + nt*8 + 2*tid]);
    }

#pragma unroll
    for (int mt = 0; mt < 2; ++mt) {
        int rA = row0 + row0w + mt*16 + g;
        int rB = rA + 8;
        float p1A = 0.f, p2A = 0.f, p1B = 0.f, p2B = 0.f;
#pragma unroll
        for (int nt = 0; nt < 4; ++nt) {
            float c0v = cacc[mt][nt][0], c1v = cacc[mt][nt][1];
            float c2v = cacc[mt][nt][2], c3v = cacc[mt][nt][3];
            int colb = c0 + col0w + nt*8 + 2*tid;
            *reinterpret_cast<float2*>(&g_h[(size_t)rA*Hv + colb]) =
                make_float2(c0v, c1v);
            *reinterpret_cast<float2*>(&g_h[(size_t)rB*Hv + colb]) =
                make_float2(c2v, c3v);
            p1A += c0v*a1v[nt].x + c1v*a1v[nt].y;
            p2A += c0v*a2v[nt].x + c1v*a2v[nt].y;
            p1B += c2v*a1v[nt].x + c3v*a1v[nt].y;
            p2B += c2v*a2v[nt].x + c3v*a2v[nt].y;
        }
#pragma unroll
        for (int off = 1; off <= 2; off <<= 1) {
            p1A += __shfl_xor_sync(0xffffffffu, p1A, off);
            p2A += __shfl_xor_sync(0xffffffffu, p2A, off);
            p1B += __shfl_xor_sync(0xffffffffu, p1B, off);
            p2B += __shfl_xor_sync(0xffffffffu, p2B, off);
        }
        if (tid == 0) {
            atomicAdd(&s1[rA], p1A);  atomicAdd(&s2[rA], p2A);
            atomicAdd(&s1[rB], p1B);  atomicAdd(&s2[rB], p2B);
        }
    }
}

// ---------------------------------------------------------------------------
// K3: softmax attention + aggregation (+ fused mean on last layer)
// 256 threads = 2 groups x 128; tile 64 att-rows x 64 channels;
// thread = 4 rows x 8 cols (f32x2); groups split each staged j-chunk.
// ---------------------------------------------------------------------------
#define JCa 32
#define ATS 68
__global__ void __launch_bounds__(256)
k_gat_agg(const int* __restrict__ adj, int layer, int last)
{
    const int b  = blockIdx.z;
    const int i0 = blockIdx.x * 64;
    const int c0 = blockIdx.y * 64;
    const int t  = threadIdx.x;            // 0..255
    const int g  = t >> 7;                 // j-half group
    const int tl = t & 127;
    const int tx = tl & 7, ty = tl >> 3;
    const int lane = t & 31, warp = t >> 5;

    const float* s1 = g_zbuf + layer*2*BN;
    const float* s2 = s1 + BN;

    __shared__ __align__(16) float s2_sh[Nv];
    __shared__ __align__(16) float att[Nv * ATS];     // [j][i_local]; reused as st
    __shared__ __align__(16) float shb[2][JCa*64];    // h chunks; reused for reduction

    const uint32_t shba = (uint32_t)__cvta_generic_to_shared(shb);
    const float* hb = g_h + (size_t)b*Nv*Hv;

#define ISSUE_H(jc, buf)                                                       \
    {                                                                          \
        _Pragma("unroll")                                                      \
        for (int m = 0; m < 2; ++m) {                                          \
            int idx = t + 256*m;                                               \
            int k = idx >> 4, f = idx & 15;                                    \
            uint32_t off = ((buf)*2048 + k*64 + f*4)*4;                        \
            cp16(shba + off, &hb[(size_t)((jc)+k)*Hv + c0 + f*4]);             \
        }                                                                      \
        CP_COMMIT();                                                           \
    }

    ISSUE_H(0, 0);       // overlap with softmax

    if (t < Nv) s2_sh[t] = s2[b*Nv + t];
    __syncthreads();

    // softmax: 8 rows per warp (8 warps x 8 = 64 rows); int4 adj loads
#pragma unroll
    for (int rr = 0; rr < 8; ++rr) {
        int il = warp*8 + rr;
        int i  = i0 + il;
        float s1i = s1[b*Nv + i];
        const int* adj_row = adj + (size_t)(b*Nv + i)*Nv;
        int4   am  = *reinterpret_cast<const int4*>(&adj_row[lane*4]);
        float4 s2v = *reinterpret_cast<const float4*>(&s2_sh[lane*4]);
        float e[4];
        {
            float v0 = s1i + s2v.x, v1 = s1i + s2v.y;
            float v2 = s1i + s2v.z, v3 = s1i + s2v.w;
            v0 = (v0 > 0.f) ? v0 : ALPHA*v0;  v1 = (v1 > 0.f) ? v1 : ALPHA*v1;
            v2 = (v2 > 0.f) ? v2 : ALPHA*v2;  v3 = (v3 > 0.f) ? v3 : ALPHA*v3;
            e[0] = (am.x > 0) ? v0 : NEG_INF;
            e[1] = (am.y > 0) ? v1 : NEG_INF;
            e[2] = (am.z > 0) ? v2 : NEG_INF;
            e[3] = (am.w > 0) ? v3 : NEG_INF;
        }
        float mx = fmaxf(fmaxf(e[0], e[1]), fmaxf(e[2], e[3]));
#pragma unroll
        for (int off = 16; off > 0; off >>= 1)
            mx = fmaxf(mx, __shfl_xor_sync(0xffffffffu, mx, off));
        float sum = 0.f;
#pragma unroll
        for (int q = 0; q < 4; ++q) { e[q] = __expf(e[q] - mx); sum += e[q]; }
#pragma unroll
        for (int off = 16; off > 0; off >>= 1)
            sum += __shfl_xor_sync(0xffffffffu, sum, off);
        float inv = 1.f / sum;
#pragma unroll
        for (int q = 0; q < 4; ++q)
            att[(lane*4 + q)*ATS + il] = e[q] * inv;
    }

    u64 acc[4][4];
#pragma unroll
    for (int r = 0; r < 4; ++r)
#pragma unroll
        for (int p = 0; p < 4; ++p) acc[r][p] = pack2(0.f, 0.f);

    const int NJC = Nv / JCa;      // 4
#pragma unroll
    for (int c = 0; c < NJC; ++c) {
        const int cur = c & 1;
        if (c + 1 < NJC) {
            ISSUE_H((c+1)*JCa, (c+1)&1);
            CP_WAIT1();
        } else {
            CP_WAIT0();
        }
        __syncthreads();

#pragma unroll 8
        for (int kk = 0; kk < 16; ++kk) {
            int kc = g*16 + kk;           // index within chunk
            int j  = c*JCa + kc;          // global j
            float4 ia = *reinterpret_cast<const float4*>(&att[j*ATS + ty*4]);
            const u64* hp = reinterpret_cast<const u64*>(&shb[cur][kc*64 + tx*4]);
            const u64* hq = reinterpret_cast<const u64*>(&shb[cur][kc*64 + 32 + tx*4]);
            u64 h0 = hp[0], h1 = hp[1], h2 = hq[0], h3 = hq[1];
            u64 i0p = pack2(ia.x, ia.x);
            u64 i1p = pack2(ia.y, ia.y);
            u64 i2p = pack2(ia.z, ia.z);
            u64 i3p = pack2(ia.w, ia.w);
            fma2(acc[0][0], i0p, h0); fma2(acc[0][1], i0p, h1);
            fma2(acc[0][2], i0p, h2); fma2(acc[0][3], i0p, h3);
            fma2(acc[1][0], i1p, h0); fma2(acc[1][1], i1p, h1);
            fma2(acc[1][2], i1p, h2); fma2(acc[1][3], i1p, h3);
            fma2(acc[2][0], i2p, h0); fma2(acc[2][1], i2p, h1);
            fma2(acc[2][2], i2p, h2); fma2(acc[2][3], i2p, h3);
            fma2(acc[3][0], i3p, h0); fma2(acc[3][1], i3p, h1);
            fma2(acc[3][2], i3p, h2); fma2(acc[3][3], i3p, h3);
        }
        __syncthreads();
    }
#undef ISSUE_H

    // split-j reduction through smem (reuse shb: 2048 u64 = 16KB)
    u64* red = reinterpret_cast<u64*>(shb);
    if (g == 1) {
#pragma unroll
        for (int r = 0; r < 4; ++r)
#pragma unroll
            for (int p = 0; p < 4; ++p)
                red[(r*4 + p)*128 + tl] = acc[r][p];
    }
    __syncthreads();

    if (last) {
        if (g == 0) {
            float* graph = g_zbuf + GRAPH_OFF;
            float colsum[8];
#pragma unroll
            for (int q = 0; q < 8; ++q) colsum[q] = 0.f;
#pragma unroll
            for (int r = 0; r < 4; ++r) {
#pragma unroll
                for (int p = 0; p < 4; ++p)
                    acc[r][p] = add2(acc[r][p], red[(r*4 + p)*128 + tl]);
                float2 v0 = unpack2(acc[r][0]);
                float2 v1 = unpack2(acc[r][1]);
                float2 v2 = unpack2(acc[r][2]);
                float2 v3 = unpack2(acc[r][3]);
                colsum[0] += fmaxf(v0.x, 0.f); colsum[1] += fmaxf(v0.y, 0.f);
                colsum[2] += fmaxf(v1.x, 0.f); colsum[3] += fmaxf(v1.y, 0.f);
                colsum[4] += fmaxf(v2.x, 0.f); colsum[5] += fmaxf(v2.y, 0.f);
                colsum[6] += fmaxf(v3.x, 0.f); colsum[7] += fmaxf(v3.y, 0.f);
            }
#pragma unroll
            for (int q = 0; q < 8; ++q) {
                int col = (q < 4) ? (tx*4 + q) : (32 + tx*4 + q - 4);
                atomicAdd(&graph[b*Hv + c0 + col], colsum[q]);
            }
        }
    } else {
        // group 0 reduces + writes st[i][c] (att reuse); all 256 store split x
        float* st = att;
        if (g == 0) {
#pragma unroll
            for (int r = 0; r < 4; ++r) {
#pragma unroll
                for (int p = 0; p < 4; ++p)
                    acc[r][p] = add2(acc[r][p], red[(r*4 + p)*128 + tl]);
                int il = ty*4 + r;
                float2 v0 = unpack2(acc[r][0]);
                float2 v1 = unpack2(acc[r][1]);
                float2 v2 = unpack2(acc[r][2]);
                float2 v3 = unpack2(acc[r][3]);
                st[il*ATS + tx*4 + 0]      = fmaxf(v0.x, 0.f);
                st[il*ATS + tx*4 + 1]      = fmaxf(v0.y, 0.f);
                st[il*ATS + tx*4 + 2]      = fmaxf(v1.x, 0.f);
                st[il*ATS + tx*4 + 3]      = fmaxf(v1.y, 0.f);
                st[il*ATS + 32 + tx*4 + 0] = fmaxf(v2.x, 0.f);
                st[il*ATS + 32 + tx*4 + 1] = fmaxf(v2.y, 0.f);
                st[il*ATS + 32 + tx*4 + 2] = fmaxf(v3.x, 0.f);
                st[il*ATS + 32 + tx*4 + 3] = fmaxf(v3.y, 0.f);
            }
        }
        __syncthreads();
        // thread t: channel ch = t&63, quarter qt = t>>6 -> 16 rows each
        int ch = t & 63;
        int qt = t >> 6;
        size_t base = (size_t)(c0 + ch)*BN + b*Nv + i0 + qt*16;
#pragma unroll
        for (int q = 0; q < 4; ++q) {
            int i = qt*16 + 4*q;
            float4 hiv, lov;
            tf32split(st[(i+0)*ATS + ch], hiv.x, lov.x);
            tf32split(st[(i+1)*ATS + ch], hiv.y, lov.y);
            tf32split(st[(i+2)*ATS + ch], hiv.z, lov.z);
            tf32split(st[(i+3)*ATS + ch], hiv.w, lov.w);
            *reinterpret_cast<float4*>(&g_xhi[base + 4*q]) = hiv;
            *reinterpret_cast<float4*>(&g_xlo[base + 4*q]) = lov;
        }
    }
}

// ---------------------------------------------------------------------------
// K5: fused head. One block per batch element.
// ---------------------------------------------------------------------------
__global__ void k_head(const float* __restrict__ scaffold,
                       const float* __restrict__ W_sc,
                       const float* __restrict__ b_sc,
                       const float* __restrict__ gp_w1,
                       const float* __restrict__ gp_b1,
                       const float* __restrict__ gp_w2,
                       const float* __restrict__ gp_b2,
                       const float* __restrict__ out_w1,
                       const float* __restrict__ out_b1,
                       const float* __restrict__ out_w2,
                       const float* __restrict__ out_b2,
                       float* __restrict__ out)
{
    int b = blockIdx.x, t = threadIdx.x;
    const float* graph = g_zbuf + GRAPH_OFF;
    __shared__ float scaf[Sv];
    __shared__ float grow[Hv];
    __shared__ float sc[Hv];
    __shared__ float g1[128], sp1[128];
    __shared__ float c[128];
    __shared__ float hdn[128];

    if (t < Sv) scaf[t] = scaffold[b*Sv + t];
    grow[t] = graph[b*Hv + t] * (1.0f/Nv);
    __syncthreads();

    {
        float acc = b_sc[t];
#pragma unroll
        for (int k = 0; k < Sv; ++k)
            acc += scaf[k] * W_sc[k*Hv + t];
        sc[t] = acc;
    }
    __syncthreads();

    {
        int col = t & 127;
        const float* src = (t < 128) ? grow : sc;
        float acc = gp_b1[col];
#pragma unroll 4
        for (int k = 0; k < Hv; ++k)
            acc += src[k] * gp_w1[k*128 + col];
        acc = fmaxf(acc, 0.f);
        if (t < 128) g1[col] = acc; else sp1[col] = acc;
    }
    __syncthreads();

    if (t < 128) {
        int col = t & 63;
        const float* src = (t < 64) ? g1 : sp1;
        float acc = gp_b2[col];
#pragma unroll 4
        for (int k = 0; k < 128; ++k)
            acc += src[k] * gp_w2[k*64 + col];
        c[t] = fmaxf(acc, 0.f);
    }
    __syncthreads();

    if (t < 128) {
        float acc = out_b1[t];
#pragma unroll 4
        for (int k = 0; k < 128; ++k)
            acc += c[k] * out_w1[k*128 + t];
        hdn[t] = fmaxf(acc, 0.f);
    }
    __syncthreads();

    if (t < Tv) {
        float acc = out_b2[t];
#pragma unroll 4
        for (int k = 0; k < 128; ++k)
            acc += hdn[k] * out_w2[k*Tv + t];
        out[b*Tv + t] = acc;
    }
}

// ---------------------------------------------------------------------------
extern "C" void kernel_launch(void* const* d_in, const int* in_sizes, int n_in,
                              void* d_out, int out_size)
{
    const float* node_features     = (const float*)d_in[0];
    // d_in[1] = edge_features — unused by the reference
    const int*   adj_matrix        = (const int*)  d_in[2];
    const float* scaffold_features = (const float*)d_in[3];
    const float* W_node            = (const float*)d_in[4];
    const float* b_node            = (const float*)d_in[5];
    const float* gat_W             = (const float*)d_in[6];
    const float* gat_a             = (const float*)d_in[7];
    const float* W_sc              = (const float*)d_in[8];
    const float* b_sc              = (const float*)d_in[9];
    const float* gp_w1             = (const float*)d_in[10];
    const float* gp_b1             = (const float*)d_in[11];
    const float* gp_w2             = (const float*)d_in[12];
    const float* gp_b2             = (const float*)d_in[13];
    const float* out_w1            = (const float*)d_in[14];
    const float* out_b1            = (const float*)d_in[15];
    const float* out_w2            = (const float*)d_in[16];
    const float* out_b2            = (const float*)d_in[17];
    float* out = (float*)d_out;

    void* zp = nullptr;
    cudaGetSymbolAddress(&zp, g_zbuf);
    cudaMemsetAsync(zp, 0, (Lv*2*BN + Bv*Hv)*sizeof(float));

    k_split_w<<<Lv*Hv*Hv/256, 256>>>(gat_W);
    k_node_proj<<<BN/NP_ROWS, 256>>>(node_features, W_node, b_node);

    for (int l = 0; l < Lv; ++l) {
        dim3 pg(BN/64, Hv/64);                 // 64 x 4 = 256 blocks, 128 thr
        k_gat_proj<<<pg, 128>>>(gat_a + (size_t)l*2*Hv, l);
        dim3 ag(Nv/64, Hv/64, Bv);             // 2 x 4 x 32 = 256 blocks, 256 thr
        k_gat_agg<<<ag, 256>>>(adj_matrix, l, l == Lv-1);
    }

    k_head<<<Bv, 256>>>(scaffold_features, W_sc, b_sc,
                        gp_w1, gp_b1, gp_w2, gp_b2,
                        out_w1, out_b1, out_w2, out_b2, out);
}